// round 14
// baseline (speedup 1.0000x reference)
#include <cuda_runtime.h>
#include <cuda_fp16.h>
#include <math.h>

#define SVAL 64
#define DIM 256
#define PD 260                    // padded dim: data at [2,257], zero skirt
#define PD2 (PD * PD)
#define PVOX (PD * PD * PD)       // 70.3MB < L2 (126MB): residency load-bearing
#define GROUPS_PER_ROW (PD / 4)

__device__ __half2 g_pad[PVOX];

// L2-evict-first loads (policy form; L1 policy default — R9 lesson)
__device__ __forceinline__ float4 ld4_l2ef(const float* p)
{
    float4 v;
    asm volatile(
        "{\n\t"
        ".reg .b64 pol;\n\t"
        "createpolicy.fractional.L2::evict_first.b64 pol, 1.0;\n\t"
        "ld.global.L2::cache_hint.v4.f32 {%0,%1,%2,%3}, [%4], pol;\n\t"
        "}"
        : "=f"(v.x), "=f"(v.y), "=f"(v.z), "=f"(v.w) : "l"(p));
    return v;
}

// ---- prepass: zero-padded x-dup half2 volume (fat threads, R9-validated) ----
__global__ __launch_bounds__(256) void build_pad_kernel(const float* __restrict__ vol)
{
    const int t = blockIdx.x * blockDim.x + threadIdx.x;
    if (t >= PD2 * GROUPS_PER_ROW) return;

    const int row = t / GROUPS_PER_ROW;
    const int g   = t - row * GROUPS_PER_ROW;
    const int zi  = row / PD;
    const int yi  = row - zi * PD;
    const int z = zi - 2, y = yi - 2;

    uint4* outp = (uint4*)((unsigned*)g_pad + (size_t)row * PD) + g;

    const bool real = ((unsigned)z < 256u) & ((unsigned)y < 256u);
    if (!real) {
        *outp = make_uint4(0u, 0u, 0u, 0u);
        return;
    }

    const float4* vrow4 = (const float4*)(vol + ((size_t)z * DIM + y) * DIM);
    const float4 Z4 = make_float4(0.f, 0.f, 0.f, 0.f);
    const float4 A = (g >= 1) ? __ldg(vrow4 + (g - 1)) : Z4;
    const float4 B = (g <= (DIM / 4) - 1) ? __ldg(vrow4 + g) : Z4;

    const float vals[8] = { A.x, A.y, A.z, A.w, B.x, B.y, B.z, B.w };

    uint4 o;
    {
        __half2 h0 = __floats2half2_rn(vals[2], vals[3]);
        __half2 h1 = __floats2half2_rn(vals[3], vals[4]);
        __half2 h2 = __floats2half2_rn(vals[4], vals[5]);
        __half2 h3 = __floats2half2_rn(vals[5], vals[6]);
        o.x = *(unsigned*)&h0;
        o.y = *(unsigned*)&h1;
        o.z = *(unsigned*)&h2;
        o.w = *(unsigned*)&h3;
    }
    *outp = o;
}

// ---- main kernel: 2 rays per warp, 16 lanes x 4 samples each ----
__global__ __launch_bounds__(256, 6) void psf_sample_kernel(
    const float* __restrict__ sampleGrid, // [N,3]
    const float* __restrict__ ax,         // [N,6]
    const float* __restrict__ bound,      // [N,2,3]
    const float* __restrict__ invcov,     // [3,3]
    const float* __restrict__ xyz_psf,    // [N,S,3]
    float* __restrict__ out,              // [N]
    int N)
{
    const int warps_per_block = blockDim.x >> 5;
    const int w = blockIdx.x * warps_per_block + (threadIdx.x >> 5);
    if (2 * w >= N) return;
    const int lane = threadIdx.x & 31;
    const int half = lane >> 4;           // which ray in this warp
    const int hl   = lane & 15;           // lane within half-warp
    const int n = min(2 * w + half, N - 1);  // odd-N tail: both halves same ray (same value)

    // ---- psf loads: 4 consecutive samples/lane = 12 contiguous floats, 48B-aligned ----
    const float* pb = xyz_psf + (size_t)n * (SVAL * 3) + hl * 12;
    const float4 p0 = ld4_l2ef(pb + 0);
    const float4 p1 = ld4_l2ef(pb + 4);
    const float4 p2 = ld4_l2ef(pb + 8);
    const float el[12] = { p0.x, p0.y, p0.z, p0.w,
                           p1.x, p1.y, p1.z, p1.w,
                           p2.x, p2.y, p2.z, p2.w };

    // ---- per-ray uniform setup (shared instruction stream serves both rays) ----
    const float vx = __ldg(ax + (size_t)n * 6 + 0);
    const float vy = __ldg(ax + (size_t)n * 6 + 1);
    const float vz = __ldg(ax + (size_t)n * 6 + 2);
    const float tx = __ldg(ax + (size_t)n * 6 + 3);
    const float ty = __ldg(ax + (size_t)n * 6 + 4);
    const float tz = __ldg(ax + (size_t)n * 6 + 5);

    const float theta = sqrtf(vx * vx + vy * vy + vz * vz);
    const float invt = 1.0f / fmaxf(theta, 1e-12f);
    const float kx = vx * invt, ky = vy * invt, kz = vz * invt;
    const float st = sinf(theta);
    const float ct = cosf(theta);
    const float oc = 1.0f - ct;

    const float r00 = 1.0f - oc * (ky * ky + kz * kz);
    const float r01 = -st * kz + oc * kx * ky;
    const float r02 =  st * ky + oc * kx * kz;
    const float r10 =  st * kz + oc * kx * ky;
    const float r11 = 1.0f - oc * (kx * kx + kz * kz);
    const float r12 = -st * kx + oc * ky * kz;
    const float r20 = -st * ky + oc * kx * kz;
    const float r21 =  st * kx + oc * ky * kz;
    const float r22 = 1.0f - oc * (kx * kx + ky * ky);

    const float sgx = __ldg(sampleGrid + (size_t)n * 3 + 0);
    const float sgy = __ldg(sampleGrid + (size_t)n * 3 + 1);
    const float sgz = __ldg(sampleGrid + (size_t)n * 3 + 2);

    const float px = sgx + tx, py = sgy + ty, pz = sgz + tz;
    const float cx = r00 * px + r01 * py + r02 * pz;
    const float cy = r10 * px + r11 * py + r12 * pz;
    const float cz = r20 * px + r21 * py + r22 * pz;

    const float hx = 0.5f * (__ldg(bound + (size_t)n * 6 + 3) - __ldg(bound + (size_t)n * 6 + 0));
    const float hy = 0.5f * (__ldg(bound + (size_t)n * 6 + 4) - __ldg(bound + (size_t)n * 6 + 1));
    const float hz = 0.5f * (__ldg(bound + (size_t)n * 6 + 5) - __ldg(bound + (size_t)n * 6 + 2));

    const float c00 = __ldg(invcov + 0), c01 = __ldg(invcov + 1), c02 = __ldg(invcov + 2);
    const float c10 = __ldg(invcov + 3), c11 = __ldg(invcov + 4), c12 = __ldg(invcov + 5);
    const float c20 = __ldg(invcov + 6), c21 = __ldg(invcov + 7), c22 = __ldg(invcov + 8);

    float sum_vw = 0.0f;
    float sum_w = 0.0f;

    const float SCL = 256.0f / 255.0f;   // pix = world*SCL - 0.5

#pragma unroll
    for (int k = 0; k < 4; k++) {
        const float ex = el[3 * k + 0] * hx;
        const float ey = el[3 * k + 1] * hy;
        const float ez = el[3 * k + 2] * hz;

        const float pixx = fmaf(cx + ex, SCL, -0.5f);
        const float pixy = fmaf(cy + ey, SCL, -0.5f);
        const float pixz = fmaf(cz + ez, SCL, -0.5f);

        const float fx0 = floorf(pixx), fy0 = floorf(pixy), fz0 = floorf(pixz);
        const int x0 = (int)fx0, y0 = (int)fy0, z0 = (int)fz0;
        const float fx = pixx - fx0, fy = pixy - fy0, fz = pixz - fz0;

        // padded indices; OOB lands in zero skirt (reference semantics)
        const int xi = min(max(x0 + 2, 0), PD - 2);
        const int yi = min(max(y0 + 2, 0), PD - 2);
        const int zi = min(max(z0 + 2, 0), PD - 2);

        const int b = (zi * PD + yi) * PD + xi;

        const float2 f00 = __half22float2(__ldg(g_pad + b));
        const float2 f01 = __half22float2(__ldg(g_pad + b + PD));
        const float2 f10 = __half22float2(__ldg(g_pad + b + PD2));
        const float2 f11 = __half22float2(__ldg(g_pad + b + PD2 + PD));

        const float xi00 = fmaf(fx, f00.y - f00.x, f00.x);
        const float xi01 = fmaf(fx, f01.y - f01.x, f01.x);
        const float xi10 = fmaf(fx, f10.y - f10.x, f10.x);
        const float xi11 = fmaf(fx, f11.y - f11.x, f11.x);
        const float yi0 = fmaf(fy, xi01 - xi00, xi00);
        const float yi1 = fmaf(fy, xi11 - xi10, xi10);
        const float val = fmaf(fz, yi1 - yi0, yi0);

        const float q =
            ex * (c00 * ex + c01 * ey + c02 * ez) +
            ey * (c10 * ex + c11 * ey + c12 * ez) +
            ez * (c20 * ex + c21 * ey + c22 * ez);
        const float w2 = __expf(-0.5f * q);

        sum_vw = fmaf(w2, val, sum_vw);
        sum_w += w2;
    }

    // reduce within each half-warp (offsets stay inside the 16-lane group)
#pragma unroll
    for (int off = 8; off > 0; off >>= 1) {
        sum_vw += __shfl_xor_sync(0xFFFFFFFFu, sum_vw, off);
        sum_w  += __shfl_xor_sync(0xFFFFFFFFu, sum_w, off);
    }

    if (hl == 0) {
        out[n] = sum_vw / sum_w;   // lanes 0 and 16 write consecutive rays
    }
}

extern "C" void kernel_launch(void* const* d_in, const int* in_sizes, int n_in,
                              void* d_out, int out_size)
{
    const float* x          = (const float*)d_in[0];
    const float* sampleGrid = (const float*)d_in[1];
    const float* ax         = (const float*)d_in[2];
    const float* bound      = (const float*)d_in[3];
    const float* invcov     = (const float*)d_in[4];
    const float* xyz_psf    = (const float*)d_in[5];
    float* out = (float*)d_out;

    const int N = in_sizes[1] / 3;

    // prepass: zero-padded x-dup half2 volume (70.3MB, L2-resident)
    {
        const int total = PD2 * GROUPS_PER_ROW;
        build_pad_kernel<<<(total + 255) / 256, 256>>>(x);
    }

    // main kernel: 2 rays per warp
    {
        const int threads = 256;
        const int warps_per_block = threads / 32;
        const int rays_per_block = 2 * warps_per_block;
        const int blocks = (N + rays_per_block - 1) / rays_per_block;
        psf_sample_kernel<<<blocks, threads>>>(sampleGrid, ax, bound, invcov,
                                               xyz_psf, out, N);
    }
}

// round 16
// speedup vs baseline: 1.0892x; 1.0892x over previous
#include <cuda_runtime.h>
#include <cuda_fp16.h>
#include <math.h>

#define SVAL 64
#define DIM 256
#define PD 260                    // padded dim: data at [2,257], zero skirt
#define PD2 (PD * PD)
#define PVOX (PD * PD * PD)       // 70.3MB < L2 (126MB): residency load-bearing
#define GROUPS_PER_ROW (PD / 4)

__device__ __half2 g_pad[PVOX];

// L2-evict-first (policy form); L1 policy default (R9 lesson)
__device__ __forceinline__ float ld_l2ef(const float* p)
{
    float v;
    asm volatile(
        "{\n\t"
        ".reg .b64 pol;\n\t"
        "createpolicy.fractional.L2::evict_first.b64 pol, 1.0;\n\t"
        "ld.global.L2::cache_hint.f32 %0, [%1], pol;\n\t"
        "}"
        : "=f"(v) : "l"(p));
    return v;
}

// ---- prepass: zero-padded x-dup half2 volume (fat threads, R9-validated) ----
__global__ __launch_bounds__(256) void build_pad_kernel(const float* __restrict__ vol)
{
    const int t = blockIdx.x * blockDim.x + threadIdx.x;
    if (t >= PD2 * GROUPS_PER_ROW) return;

    const int row = t / GROUPS_PER_ROW;
    const int g   = t - row * GROUPS_PER_ROW;
    const int zi  = row / PD;
    const int yi  = row - zi * PD;
    const int z = zi - 2, y = yi - 2;

    uint4* outp = (uint4*)((unsigned*)g_pad + (size_t)row * PD) + g;

    const bool real = ((unsigned)z < 256u) & ((unsigned)y < 256u);
    if (!real) {
        *outp = make_uint4(0u, 0u, 0u, 0u);
        return;
    }

    const float4* vrow4 = (const float4*)(vol + ((size_t)z * DIM + y) * DIM);
    const float4 Z4 = make_float4(0.f, 0.f, 0.f, 0.f);
    const float4 A = (g >= 1) ? __ldg(vrow4 + (g - 1)) : Z4;
    const float4 B = (g <= (DIM / 4) - 1) ? __ldg(vrow4 + g) : Z4;

    const float vals[8] = { A.x, A.y, A.z, A.w, B.x, B.y, B.z, B.w };

    uint4 o;
    {
        __half2 h0 = __floats2half2_rn(vals[2], vals[3]);
        __half2 h1 = __floats2half2_rn(vals[3], vals[4]);
        __half2 h2 = __floats2half2_rn(vals[4], vals[5]);
        __half2 h3 = __floats2half2_rn(vals[5], vals[6]);
        o.x = *(unsigned*)&h0;
        o.y = *(unsigned*)&h1;
        o.z = *(unsigned*)&h2;
        o.w = *(unsigned*)&h3;
    }
    *outp = o;
}

// ---- main kernel: warp per ray, software-pipelined 8-load batch ----
__global__ __launch_bounds__(256) void psf_sample_kernel(
    const float* __restrict__ sampleGrid, // [N,3]
    const float* __restrict__ ax,         // [N,6]
    const float* __restrict__ bound,      // [N,2,3]
    const float* __restrict__ invcov,     // [3,3]
    const float* __restrict__ xyz_psf,    // [N,S,3]
    float* __restrict__ out,              // [N]
    int N)
{
    const int warps_per_block = blockDim.x >> 5;
    const int n = blockIdx.x * warps_per_block + (threadIdx.x >> 5);
    if (n >= N) return;
    const int lane = threadIdx.x & 31;

    // ---- hoist psf loads ----
    const float* psf_base = xyz_psf + (size_t)n * SVAL * 3;
    float pe[2][3];
#pragma unroll
    for (int rep = 0; rep < 2; rep++) {
        const int s = lane + rep * 32;
        pe[rep][0] = ld_l2ef(psf_base + s * 3 + 0);
        pe[rep][1] = ld_l2ef(psf_base + s * 3 + 1);
        pe[rep][2] = ld_l2ef(psf_base + s * 3 + 2);
    }

    // ---- per-ray uniform setup (broadcast loads) ----
    const float vx = __ldg(ax + (size_t)n * 6 + 0);
    const float vy = __ldg(ax + (size_t)n * 6 + 1);
    const float vz = __ldg(ax + (size_t)n * 6 + 2);
    const float tx = __ldg(ax + (size_t)n * 6 + 3);
    const float ty = __ldg(ax + (size_t)n * 6 + 4);
    const float tz = __ldg(ax + (size_t)n * 6 + 5);

    const float theta = sqrtf(vx * vx + vy * vy + vz * vz);
    const float invt = 1.0f / fmaxf(theta, 1e-12f);
    const float kx = vx * invt, ky = vy * invt, kz = vz * invt;
    const float st = sinf(theta);
    const float ct = cosf(theta);
    const float oc = 1.0f - ct;

    const float r00 = 1.0f - oc * (ky * ky + kz * kz);
    const float r01 = -st * kz + oc * kx * ky;
    const float r02 =  st * ky + oc * kx * kz;
    const float r10 =  st * kz + oc * kx * ky;
    const float r11 = 1.0f - oc * (kx * kx + kz * kz);
    const float r12 = -st * kx + oc * ky * kz;
    const float r20 = -st * ky + oc * kx * kz;
    const float r21 =  st * kx + oc * ky * kz;
    const float r22 = 1.0f - oc * (kx * kx + ky * ky);

    const float sgx = __ldg(sampleGrid + (size_t)n * 3 + 0);
    const float sgy = __ldg(sampleGrid + (size_t)n * 3 + 1);
    const float sgz = __ldg(sampleGrid + (size_t)n * 3 + 2);

    const float px = sgx + tx, py = sgy + ty, pz = sgz + tz;
    const float cx = r00 * px + r01 * py + r02 * pz;
    const float cy = r10 * px + r11 * py + r12 * pz;
    const float cz = r20 * px + r21 * py + r22 * pz;

    const float hx = 0.5f * (__ldg(bound + (size_t)n * 6 + 3) - __ldg(bound + (size_t)n * 6 + 0));
    const float hy = 0.5f * (__ldg(bound + (size_t)n * 6 + 4) - __ldg(bound + (size_t)n * 6 + 1));
    const float hz = 0.5f * (__ldg(bound + (size_t)n * 6 + 5) - __ldg(bound + (size_t)n * 6 + 2));

    const float c00 = __ldg(invcov + 0), c01 = __ldg(invcov + 1), c02 = __ldg(invcov + 2);
    const float c10 = __ldg(invcov + 3), c11 = __ldg(invcov + 4), c12 = __ldg(invcov + 5);
    const float c20 = __ldg(invcov + 6), c21 = __ldg(invcov + 7), c22 = __ldg(invcov + 8);

    const float SCL = 256.0f / 255.0f;

    // ---- phase 1: both samples' coordinates + base indices ----
    float ex[2], ey[2], ez[2], fx[2], fy[2], fz[2];
    int base[2];
#pragma unroll
    for (int rep = 0; rep < 2; rep++) {
        ex[rep] = pe[rep][0] * hx;
        ey[rep] = pe[rep][1] * hy;
        ez[rep] = pe[rep][2] * hz;

        const float pixx = fmaf(cx + ex[rep], SCL, -0.5f);
        const float pixy = fmaf(cy + ey[rep], SCL, -0.5f);
        const float pixz = fmaf(cz + ez[rep], SCL, -0.5f);

        const float fx0 = floorf(pixx), fy0 = floorf(pixy), fz0 = floorf(pixz);
        fx[rep] = pixx - fx0;
        fy[rep] = pixy - fy0;
        fz[rep] = pixz - fz0;

        const int xi = min(max((int)fx0 + 2, 0), PD - 2);
        const int yi = min(max((int)fy0 + 2, 0), PD - 2);
        const int zi = min(max((int)fz0 + 2, 0), PD - 2);
        base[rep] = (zi * PD + yi) * PD + xi;
    }

    // ---- phase 2: issue all 8 gather loads back-to-back (MLP=8) ----
    __half2 d[2][4];
#pragma unroll
    for (int rep = 0; rep < 2; rep++) {
        const int b = base[rep];
        d[rep][0] = __ldg(g_pad + b);
        d[rep][1] = __ldg(g_pad + b + PD);
        d[rep][2] = __ldg(g_pad + b + PD2);
        d[rep][3] = __ldg(g_pad + b + PD2 + PD);
    }

    // ---- phase 3: all math ----
    float sum_vw = 0.0f;
    float sum_w = 0.0f;
#pragma unroll
    for (int rep = 0; rep < 2; rep++) {
        const float2 f00 = __half22float2(d[rep][0]);
        const float2 f01 = __half22float2(d[rep][1]);
        const float2 f10 = __half22float2(d[rep][2]);
        const float2 f11 = __half22float2(d[rep][3]);

        const float fxr = fx[rep], fyr = fy[rep], fzr = fz[rep];

        const float xi00 = fmaf(fxr, f00.y - f00.x, f00.x);
        const float xi01 = fmaf(fxr, f01.y - f01.x, f01.x);
        const float xi10 = fmaf(fxr, f10.y - f10.x, f10.x);
        const float xi11 = fmaf(fxr, f11.y - f11.x, f11.x);
        const float yi0 = fmaf(fyr, xi01 - xi00, xi00);
        const float yi1 = fmaf(fyr, xi11 - xi10, xi10);
        const float val = fmaf(fzr, yi1 - yi0, yi0);

        const float exr = ex[rep], eyr = ey[rep], ezr = ez[rep];
        const float q =
            exr * (c00 * exr + c01 * eyr + c02 * ezr) +
            eyr * (c10 * exr + c11 * eyr + c12 * ezr) +
            ezr * (c20 * exr + c21 * eyr + c22 * ezr);
        const float w2 = __expf(-0.5f * q);

        sum_vw = fmaf(w2, val, sum_vw);
        sum_w += w2;
    }

#pragma unroll
    for (int off = 16; off > 0; off >>= 1) {
        sum_vw += __shfl_xor_sync(0xFFFFFFFFu, sum_vw, off);
        sum_w  += __shfl_xor_sync(0xFFFFFFFFu, sum_w, off);
    }

    if (lane == 0) {
        out[n] = sum_vw / sum_w;
    }
}

extern "C" void kernel_launch(void* const* d_in, const int* in_sizes, int n_in,
                              void* d_out, int out_size)
{
    const float* x          = (const float*)d_in[0];
    const float* sampleGrid = (const float*)d_in[1];
    const float* ax         = (const float*)d_in[2];
    const float* bound      = (const float*)d_in[3];
    const float* invcov     = (const float*)d_in[4];
    const float* xyz_psf    = (const float*)d_in[5];
    float* out = (float*)d_out;

    const int N = in_sizes[1] / 3;

    // prepass: zero-padded x-dup half2 volume (70.3MB, L2-resident)
    {
        const int total = PD2 * GROUPS_PER_ROW;
        build_pad_kernel<<<(total + 255) / 256, 256>>>(x);
    }

    // main kernel: warp per ray
    {
        const int threads = 256;
        const int warps_per_block = threads / 32;
        const int blocks = (N + warps_per_block - 1) / warps_per_block;
        psf_sample_kernel<<<blocks, threads>>>(sampleGrid, ax, bound, invcov,
                                               xyz_psf, out, N);
    }
}

// round 17
// speedup vs baseline: 1.1136x; 1.0225x over previous
#include <cuda_runtime.h>
#include <cuda_fp16.h>
#include <math.h>

#define SVAL 64
#define DIM 256
#define PD 260                    // padded dim: data at [2,257], zero skirt
#define PD2 (PD * PD)
#define PVOX (PD * PD * PD)       // 70.3MB < L2 (126MB): residency load-bearing
#define GROUPS_PER_ROW (PD / 4)

__device__ __half2 g_pad[PVOX];

// L2-evict-first scalar load (policy form; L1 default — R9 lesson)
__device__ __forceinline__ float ld_l2ef(const float* p)
{
    float v;
    asm volatile(
        "{\n\t"
        ".reg .b64 pol;\n\t"
        "createpolicy.fractional.L2::evict_first.b64 pol, 1.0;\n\t"
        "ld.global.L2::cache_hint.f32 %0, [%1], pol;\n\t"
        "}"
        : "=f"(v) : "l"(p));
    return v;
}

// L2-evict-first vector load for the prepass vol stream (R17: keeps g_pad
// L2-resident across graph replays instead of thrashing against it)
__device__ __forceinline__ float4 ld4_l2ef(const float4* p)
{
    float4 v;
    asm volatile(
        "{\n\t"
        ".reg .b64 pol;\n\t"
        "createpolicy.fractional.L2::evict_first.b64 pol, 1.0;\n\t"
        "ld.global.L2::cache_hint.v4.f32 {%0,%1,%2,%3}, [%4], pol;\n\t"
        "}"
        : "=f"(v.x), "=f"(v.y), "=f"(v.z), "=f"(v.w) : "l"(p));
    return v;
}

// ---- prepass: zero-padded x-dup half2 volume (fat threads; vol reads stream) ----
__global__ __launch_bounds__(256) void build_pad_kernel(const float* __restrict__ vol)
{
    const int t = blockIdx.x * blockDim.x + threadIdx.x;
    if (t >= PD2 * GROUPS_PER_ROW) return;

    const int row = t / GROUPS_PER_ROW;
    const int g   = t - row * GROUPS_PER_ROW;
    const int zi  = row / PD;
    const int yi  = row - zi * PD;
    const int z = zi - 2, y = yi - 2;

    uint4* outp = (uint4*)((unsigned*)g_pad + (size_t)row * PD) + g;

    const bool real = ((unsigned)z < 256u) & ((unsigned)y < 256u);
    if (!real) {
        *outp = make_uint4(0u, 0u, 0u, 0u);
        return;
    }

    const float4* vrow4 = (const float4*)(vol + ((size_t)z * DIM + y) * DIM);
    const float4 Z4 = make_float4(0.f, 0.f, 0.f, 0.f);
    const float4 A = (g >= 1) ? ld4_l2ef(vrow4 + (g - 1)) : Z4;
    const float4 B = (g <= (DIM / 4) - 1) ? ld4_l2ef(vrow4 + g) : Z4;

    const float vals[8] = { A.x, A.y, A.z, A.w, B.x, B.y, B.z, B.w };

    uint4 o;
    {
        __half2 h0 = __floats2half2_rn(vals[2], vals[3]);
        __half2 h1 = __floats2half2_rn(vals[3], vals[4]);
        __half2 h2 = __floats2half2_rn(vals[4], vals[5]);
        __half2 h3 = __floats2half2_rn(vals[5], vals[6]);
        o.x = *(unsigned*)&h0;
        o.y = *(unsigned*)&h1;
        o.z = *(unsigned*)&h2;
        o.w = *(unsigned*)&h3;
    }
    *outp = o;
}

// ---- main kernel: warp per ray (R11 body, unchanged) ----
__global__ __launch_bounds__(256) void psf_sample_kernel(
    const float* __restrict__ sampleGrid, // [N,3]
    const float* __restrict__ ax,         // [N,6]
    const float* __restrict__ bound,      // [N,2,3]
    const float* __restrict__ invcov,     // [3,3]
    const float* __restrict__ xyz_psf,    // [N,S,3]
    float* __restrict__ out,              // [N]
    int N)
{
    const int warps_per_block = blockDim.x >> 5;
    const int n = blockIdx.x * warps_per_block + (threadIdx.x >> 5);
    if (n >= N) return;
    const int lane = threadIdx.x & 31;

    // ---- hoist psf loads: DRAM latency overlaps the setup math below ----
    const float* psf_base = xyz_psf + (size_t)n * SVAL * 3;
    float pe[2][3];
#pragma unroll
    for (int rep = 0; rep < 2; rep++) {
        const int s = lane + rep * 32;
        pe[rep][0] = ld_l2ef(psf_base + s * 3 + 0);
        pe[rep][1] = ld_l2ef(psf_base + s * 3 + 1);
        pe[rep][2] = ld_l2ef(psf_base + s * 3 + 2);
    }

    // ---- per-ray uniform setup (broadcast loads) ----
    const float vx = __ldg(ax + (size_t)n * 6 + 0);
    const float vy = __ldg(ax + (size_t)n * 6 + 1);
    const float vz = __ldg(ax + (size_t)n * 6 + 2);
    const float tx = __ldg(ax + (size_t)n * 6 + 3);
    const float ty = __ldg(ax + (size_t)n * 6 + 4);
    const float tz = __ldg(ax + (size_t)n * 6 + 5);

    const float theta = sqrtf(vx * vx + vy * vy + vz * vz);
    const float invt = 1.0f / fmaxf(theta, 1e-12f);
    const float kx = vx * invt, ky = vy * invt, kz = vz * invt;
    const float st = sinf(theta);
    const float ct = cosf(theta);
    const float oc = 1.0f - ct;

    const float r00 = 1.0f - oc * (ky * ky + kz * kz);
    const float r01 = -st * kz + oc * kx * ky;
    const float r02 =  st * ky + oc * kx * kz;
    const float r10 =  st * kz + oc * kx * ky;
    const float r11 = 1.0f - oc * (kx * kx + kz * kz);
    const float r12 = -st * kx + oc * ky * kz;
    const float r20 = -st * ky + oc * kx * kz;
    const float r21 =  st * kx + oc * ky * kz;
    const float r22 = 1.0f - oc * (kx * kx + ky * ky);

    const float sgx = __ldg(sampleGrid + (size_t)n * 3 + 0);
    const float sgy = __ldg(sampleGrid + (size_t)n * 3 + 1);
    const float sgz = __ldg(sampleGrid + (size_t)n * 3 + 2);

    const float px = sgx + tx, py = sgy + ty, pz = sgz + tz;
    const float cx = r00 * px + r01 * py + r02 * pz;
    const float cy = r10 * px + r11 * py + r12 * pz;
    const float cz = r20 * px + r21 * py + r22 * pz;

    const float hx = 0.5f * (__ldg(bound + (size_t)n * 6 + 3) - __ldg(bound + (size_t)n * 6 + 0));
    const float hy = 0.5f * (__ldg(bound + (size_t)n * 6 + 4) - __ldg(bound + (size_t)n * 6 + 1));
    const float hz = 0.5f * (__ldg(bound + (size_t)n * 6 + 5) - __ldg(bound + (size_t)n * 6 + 2));

    const float c00 = __ldg(invcov + 0), c01 = __ldg(invcov + 1), c02 = __ldg(invcov + 2);
    const float c10 = __ldg(invcov + 3), c11 = __ldg(invcov + 4), c12 = __ldg(invcov + 5);
    const float c20 = __ldg(invcov + 6), c21 = __ldg(invcov + 7), c22 = __ldg(invcov + 8);

    float sum_vw = 0.0f;
    float sum_w = 0.0f;

    const float SCL = 256.0f / 255.0f;   // pix = world*SCL - 0.5

#pragma unroll
    for (int rep = 0; rep < 2; rep++) {
        const float ex = pe[rep][0] * hx;
        const float ey = pe[rep][1] * hy;
        const float ez = pe[rep][2] * hz;

        const float pixx = fmaf(cx + ex, SCL, -0.5f);
        const float pixy = fmaf(cy + ey, SCL, -0.5f);
        const float pixz = fmaf(cz + ez, SCL, -0.5f);

        const float fx0 = floorf(pixx), fy0 = floorf(pixy), fz0 = floorf(pixz);
        const int x0 = (int)fx0, y0 = (int)fy0, z0 = (int)fz0;
        const float fx = pixx - fx0, fy = pixy - fy0, fz = pixz - fz0;

        // padded indices; all OOB cases land in the zero skirt
        const int xi = min(max(x0 + 2, 0), PD - 2);
        const int yi = min(max(y0 + 2, 0), PD - 2);
        const int zi = min(max(z0 + 2, 0), PD - 2);

        const int b = (zi * PD + yi) * PD + xi;

        const float2 f00 = __half22float2(__ldg(g_pad + b));
        const float2 f01 = __half22float2(__ldg(g_pad + b + PD));
        const float2 f10 = __half22float2(__ldg(g_pad + b + PD2));
        const float2 f11 = __half22float2(__ldg(g_pad + b + PD2 + PD));

        const float xi00 = fmaf(fx, f00.y - f00.x, f00.x);
        const float xi01 = fmaf(fx, f01.y - f01.x, f01.x);
        const float xi10 = fmaf(fx, f10.y - f10.x, f10.x);
        const float xi11 = fmaf(fx, f11.y - f11.x, f11.x);
        const float yi0 = fmaf(fy, xi01 - xi00, xi00);
        const float yi1 = fmaf(fy, xi11 - xi10, xi10);
        const float val = fmaf(fz, yi1 - yi0, yi0);

        const float q =
            ex * (c00 * ex + c01 * ey + c02 * ez) +
            ey * (c10 * ex + c11 * ey + c12 * ez) +
            ez * (c20 * ex + c21 * ey + c22 * ez);
        const float w = __expf(-0.5f * q);

        sum_vw = fmaf(w, val, sum_vw);
        sum_w += w;
    }

#pragma unroll
    for (int off = 16; off > 0; off >>= 1) {
        sum_vw += __shfl_xor_sync(0xFFFFFFFFu, sum_vw, off);
        sum_w  += __shfl_xor_sync(0xFFFFFFFFu, sum_w, off);
    }

    if (lane == 0) {
        out[n] = sum_vw / sum_w;
    }
}

extern "C" void kernel_launch(void* const* d_in, const int* in_sizes, int n_in,
                              void* d_out, int out_size)
{
    const float* x          = (const float*)d_in[0];
    const float* sampleGrid = (const float*)d_in[1];
    const float* ax         = (const float*)d_in[2];
    const float* bound      = (const float*)d_in[3];
    const float* invcov     = (const float*)d_in[4];
    const float* xyz_psf    = (const float*)d_in[5];
    float* out = (float*)d_out;

    const int N = in_sizes[1] / 3;

    // prepass: zero-padded x-dup half2 volume (70.3MB, L2-resident across replays)
    {
        const int total = PD2 * GROUPS_PER_ROW;
        build_pad_kernel<<<(total + 255) / 256, 256>>>(x);
    }

    // main kernel: warp per ray
    {
        const int threads = 256;
        const int warps_per_block = threads / 32;
        const int blocks = (N + warps_per_block - 1) / warps_per_block;
        psf_sample_kernel<<<blocks, threads>>>(sampleGrid, ax, bound, invcov,
                                               xyz_psf, out, N);
    }
}